// round 9
// baseline (speedup 1.0000x reference)
#include <cuda_runtime.h>
#include <cuda_fp16.h>

#define TT 512
#define SDIM 8
#define ODIM 4
#define NTHREADS 256
#define NCTA 128
#define ROWS 8
#define ROWF 72   // 64 state floats + 16B skew between k-halves + pad

typedef unsigned long long ull;

// fp16 weights as uint2 quads: arr[q][j] = {half2(4q,4q+1), half2(4q+2,4q+3)}
// f32  weights as ulonglong2 quads: {f32x2(4q,4q+1), f32x2(4q+2,4q+3)}
struct __align__(16) Smem {
    ulonglong2 Wf32[3][16][64];  // W_from_W, W_from_I, W_from_A (f32)
    ulonglong2 Ih32[3][16][64];  // I_h rows [Wn | r*I | A]      (f32)
    uint2 Wg[2][16][64];         // W_gate rows [I | A]
    uint2 Iz[3][16][64];
    uint2 Ir[3][16][64];
    uint2 Aff[3][16][64];
    uint2 Agt[2][16][64];        // rows [Wn | In]
    float sW[2][ROWS][ROWF];     // double-buffered states, skewed rows
    float sI[2][ROWS][ROWF];
    float sA[2][ROWS][ROWF];
    float sRI[ROWS][ROWF];
    float xs[ROWS][SDIM];
};

extern __shared__ char smem_raw[];

__device__ __forceinline__ float tanh_f(float x) {
    x = fminf(fmaxf(x, -9.0f), 9.0f);
    float e = __expf(2.0f * x);
    return __fdividef(e - 1.0f, e + 1.0f);
}
__device__ __forceinline__ float sigm_f(float x) {
    return __fdividef(1.0f, 1.0f + __expf(-x));
}

__device__ __forceinline__ ull h2f2(unsigned int h) {
    ull r;
    asm("{\n\t"
        ".reg .b16 l16, h16;\n\t"
        ".reg .f32 fl, fh;\n\t"
        "mov.b32 {l16, h16}, %1;\n\t"
        "cvt.f32.f16 fl, l16;\n\t"
        "cvt.f32.f16 fh, h16;\n\t"
        "mov.b64 %0, {fl, fh};\n\t"
        "}" : "=l"(r) : "r"(h));
    return r;
}
__device__ __forceinline__ ull packf2(float x, float y) {
    ull r;
    asm("mov.b64 %0, {%1, %2};" : "=l"(r) : "f"(x), "f"(y));
    return r;
}
__device__ __forceinline__ void fma2(ull& d, ull a, ull b) {
    asm("fma.rn.f32x2 %0, %1, %2, %0;" : "+l"(d) : "l"(a), "l"(b));
}
__device__ __forceinline__ float hsum2(ull a, ull b) {
    float ax, ay, bx, by;
    asm("mov.b64 {%0, %1}, %2;" : "=f"(ax), "=f"(ay) : "l"(a));
    asm("mov.b64 {%0, %1}, %2;" : "=f"(bx), "=f"(by) : "l"(b));
    return (ax + bx) + (ay + by);
}
// k-half partial -> full dot (partner lane is lane^16)
__device__ __forceinline__ float red32(ull P, ull Q) {
    float p = hsum2(P, Q);
    return p + __shfl_xor_sync(0xffffffffu, p, 16);
}
// group barrier: 128 threads of row-half group (barrier id 1 or 2)
__device__ __forceinline__ void gbar(int id) {
    asm volatile("bar.sync %0, 128;" :: "r"(id) : "memory");
}

__device__ __forceinline__ void stage4(uint2 (&dst)[16][64],
                                       const float* __restrict__ src) {
#pragma unroll 1
    for (int i = threadIdx.x; i < 1024; i += NTHREADS) {
        int q = i >> 6, jj = i & 63;
        __half2 a = __floats2half2_rn(src[(4 * q + 0) * 64 + jj],
                                      src[(4 * q + 1) * 64 + jj]);
        __half2 b = __floats2half2_rn(src[(4 * q + 2) * 64 + jj],
                                      src[(4 * q + 3) * 64 + jj]);
        uint2 v;
        v.x = *reinterpret_cast<unsigned int*>(&a);
        v.y = *reinterpret_cast<unsigned int*>(&b);
        dst[q][jj] = v;
    }
}
__device__ __forceinline__ void stage4f(ulonglong2 (&dst)[16][64],
                                        const float* __restrict__ src) {
#pragma unroll 1
    for (int i = threadIdx.x; i < 1024; i += NTHREADS) {
        int q = i >> 6, jj = i & 63;
        ulonglong2 v;
        v.x = packf2(src[(4 * q + 0) * 64 + jj], src[(4 * q + 1) * 64 + jj]);
        v.y = packf2(src[(4 * q + 2) * 64 + jj], src[(4 * q + 3) * 64 + jj]);
        dst[q][jj] = v;
    }
}

__global__ void __launch_bounds__(NTHREADS, 1)
anima_kernel(const float* __restrict__ x,
             const float* __restrict__ we_w, const float* __restrict__ we_b,
             const float* __restrict__ WfW, const float* __restrict__ WfI,
             const float* __restrict__ WfA,
             const float* __restrict__ Wg_w, const float* __restrict__ Wg_b,
             const float* __restrict__ Iz_w, const float* __restrict__ Iz_b,
             const float* __restrict__ Ir_w, const float* __restrict__ Ir_b,
             const float* __restrict__ Ih_w, const float* __restrict__ Ih_b,
             const float* __restrict__ AfW, const float* __restrict__ AfI,
             const float* __restrict__ AfA,
             const float* __restrict__ Ag_w, const float* __restrict__ Ag_b,
             const float* __restrict__ phi_w, const float* __restrict__ phi_b,
             float* __restrict__ out) {
    Smem* S = reinterpret_cast<Smem*>(smem_raw);
    const int tid = threadIdx.x;

    // ---- one-time staging
    stage4f(S->Wf32[0], WfW);
    stage4f(S->Wf32[1], WfI);
    stage4f(S->Wf32[2], WfA);
    stage4f(S->Ih32[0], Ih_w);
    stage4f(S->Ih32[1], Ih_w + 64 * 64);
    stage4f(S->Ih32[2], Ih_w + 128 * 64);
    stage4(S->Wg[0], Wg_w);
    stage4(S->Wg[1], Wg_w + 64 * 64);
    stage4(S->Iz[0], Iz_w);
    stage4(S->Iz[1], Iz_w + 64 * 64);
    stage4(S->Iz[2], Iz_w + 128 * 64);
    stage4(S->Ir[0], Ir_w);
    stage4(S->Ir[1], Ir_w + 64 * 64);
    stage4(S->Ir[2], Ir_w + 128 * 64);
    stage4(S->Aff[0], AfW);
    stage4(S->Aff[1], AfI);
    stage4(S->Aff[2], AfA);
    stage4(S->Agt[0], Ag_w);
    stage4(S->Agt[1], Ag_w + 64 * 64);

#pragma unroll 1
    for (int i = tid; i < 2 * ROWS * ROWF; i += NTHREADS) {
        (&S->sW[0][0][0])[i] = 0.f;
        (&S->sI[0][0][0])[i] = 0.f;
        (&S->sA[0][0][0])[i] = 0.f;
    }

    // ---- thread mapping: warp = (rowhalf rh, jgroup jg); lane = (kh, jj)
    const int lane = tid & 31, w = tid >> 5;
    const int jg = w & 3, rh = w >> 2;
    const int jj = lane & 15, kh = lane >> 4;
    const int j = jg * 16 + jj;
    const int js = j + ((j >> 5) << 2);   // skewed in-row offset
    const int R = rh * 4;                 // first of this thread's 4 rows
    const int khq = kh * 8;               // weight quad base
    const int khf = kh * 36;              // state float base (skewed)
    const int bid = rh + 1;               // named barrier id for this group
    const long base = (long)blockIdx.x * ROWS;

    float we[8];
#pragma unroll
    for (int s = 0; s < 8; s++) we[s] = we_w[s * 64 + j];
    const float be = we_b[j], bg = Wg_b[j], bz = Iz_b[j],
                br = Ir_b[j], bh = Ih_b[j], ba = Ag_b[j];

    // Phase-5 mapping: warp = row (group-local), lane -> (o, k-segment)
    const int wrow = w;
    const int o5 = lane & 3, seg = lane >> 2;
    float ph[8];
#pragma unroll
    for (int kk = 0; kk < 8; kk++) ph[kk] = phi_w[(seg * 8 + kk) * 4 + o5];
    const float bphi = phi_b[o5];
    const int segoff = (seg < 4) ? seg * 8 : 36 + (seg - 4) * 8;

    // x staging: group-local — 32 threads of each group stage its 4 rows
    const int ltid = tid & 127;
    const int xrow = R + (ltid >> 3), xc = ltid & 7;
    const float* xptr = x + (base + xrow) * (TT * SDIM) + xc;
    float xv = (ltid < 32) ? xptr[0] : 0.f;
    __syncthreads();
    if (ltid < 32) S->xs[xrow][xc] = xv;
    __syncthreads();

    for (int t = 0; t < TT; t++) {
        const int nb = t & 1, pb = nb ^ 1;
        if (ltid < 32 && t + 1 < TT) xv = xptr[(t + 1) * SDIM];

        const ulonglong2 *pw[4], *pi[4], *pa[4];
#pragma unroll
        for (int r = 0; r < 4; r++) {
            pw[r] = (const ulonglong2*)(S->sW[pb][R + r] + khf);
            pi[r] = (const ulonglong2*)(S->sI[pb][R + r] + khf);
            pa[r] = (const ulonglong2*)(S->sA[pb][R + r] + khf);
        }

        // ---------- Phase 1: encoder + W gate + W_in ----------
        float enc[4];
#pragma unroll
        for (int r = 0; r < 4; r++) {
            const float4* x4 = reinterpret_cast<const float4*>(S->xs[R + r]);
            float4 a = x4[0], b = x4[1];
            float e = be;
            e = fmaf(a.x, we[0], e); e = fmaf(a.y, we[1], e);
            e = fmaf(a.z, we[2], e); e = fmaf(a.w, we[3], e);
            e = fmaf(b.x, we[4], e); e = fmaf(b.y, we[5], e);
            e = fmaf(b.z, we[6], e); e = fmaf(b.w, we[7], e);
            enc[r] = tanh_f(e);
        }
        {
            ull aW[4][2] = {}, aG[4][2] = {};
#pragma unroll
            for (int q = 0; q < 8; q++) {
                const int qw = khq + q;
                ulonglong2 m0 = S->Wf32[0][qw][j];
                ulonglong2 m1 = S->Wf32[1][qw][j];
                ulonglong2 m2 = S->Wf32[2][qw][j];
                uint2 u0 = S->Wg[0][qw][j];  ull u0x = h2f2(u0.x), u0y = h2f2(u0.y);
                uint2 u1 = S->Wg[1][qw][j];  ull u1x = h2f2(u1.x), u1y = h2f2(u1.y);
#pragma unroll
                for (int r = 0; r < 4; r++) {
                    ulonglong2 vw = pw[r][q], vi = pi[r][q], va = pa[r][q];
                    fma2(aW[r][0], m0.x, vw.x); fma2(aW[r][1], m0.y, vw.y);
                    fma2(aW[r][0], m1.x, vi.x); fma2(aW[r][1], m1.y, vi.y);
                    fma2(aG[r][0], u0x, vi.x);  fma2(aG[r][1], u0y, vi.y);
                    fma2(aW[r][0], m2.x, va.x); fma2(aW[r][1], m2.y, va.y);
                    fma2(aG[r][0], u1x, va.x);  fma2(aG[r][1], u1y, va.y);
                }
            }
#pragma unroll
            for (int r = 0; r < 4; r++) {
                float win = red32(aW[r][0], aW[r][1]);
                float gin = red32(aG[r][0], aG[r][1]);
                float Wn = tanh_f(enc[r] + win) * sigm_f(bg + gin);
                if (kh == 0) S->sW[nb][R + r][js] = Wn;
            }
        }
        gbar(bid);

        const ulonglong2* pwn[4];
#pragma unroll
        for (int r = 0; r < 4; r++)
            pwn[r] = (const ulonglong2*)(S->sW[nb][R + r] + khf);

        // ---------- Phase 2: z, r gates; stash r*I ----------
        float zv[4], Iold[4];
        {
            ull aZ[4][2] = {}, aR[4][2] = {};
#pragma unroll
            for (int q = 0; q < 8; q++) {
                const int qw = khq + q;
                uint2 za = S->Iz[0][qw][j]; ull zax = h2f2(za.x), zay = h2f2(za.y);
                uint2 zb = S->Iz[1][qw][j]; ull zbx = h2f2(zb.x), zby = h2f2(zb.y);
                uint2 zc = S->Iz[2][qw][j]; ull zcx = h2f2(zc.x), zcy = h2f2(zc.y);
                uint2 ra = S->Ir[0][qw][j]; ull rax = h2f2(ra.x), ray = h2f2(ra.y);
                uint2 rb = S->Ir[1][qw][j]; ull rbx = h2f2(rb.x), rby = h2f2(rb.y);
                uint2 rc = S->Ir[2][qw][j]; ull rcx = h2f2(rc.x), rcy = h2f2(rc.y);
#pragma unroll
                for (int r = 0; r < 4; r++) {
                    ulonglong2 vw = pwn[r][q], vi = pi[r][q], va = pa[r][q];
                    fma2(aZ[r][0], zax, vw.x); fma2(aZ[r][1], zay, vw.y);
                    fma2(aR[r][0], rax, vw.x); fma2(aR[r][1], ray, vw.y);
                    fma2(aZ[r][0], zbx, vi.x); fma2(aZ[r][1], zby, vi.y);
                    fma2(aR[r][0], rbx, vi.x); fma2(aR[r][1], rby, vi.y);
                    fma2(aZ[r][0], zcx, va.x); fma2(aZ[r][1], zcy, va.y);
                    fma2(aR[r][0], rcx, va.x); fma2(aR[r][1], rcy, va.y);
                }
            }
#pragma unroll
            for (int r = 0; r < 4; r++) {
                zv[r] = sigm_f(bz + red32(aZ[r][0], aZ[r][1]));
                float rv = sigm_f(br + red32(aR[r][0], aR[r][1]));
                Iold[r] = S->sI[pb][R + r][js];
                if (kh == 0) S->sRI[R + r][js] = rv * Iold[r];
            }
        }
        gbar(bid);

        // ---------- Phase 3: h, I_new (all-f32 weights) ----------
        {
            const ulonglong2* pri[4];
#pragma unroll
            for (int r = 0; r < 4; r++)
                pri[r] = (const ulonglong2*)(S->sRI[R + r] + khf);
            ull aH[4][2] = {};
#pragma unroll
            for (int q = 0; q < 8; q++) {
                const int qw = khq + q;
                ulonglong2 ha = S->Ih32[0][qw][j];
                ulonglong2 hb = S->Ih32[1][qw][j];
                ulonglong2 hc = S->Ih32[2][qw][j];
#pragma unroll
                for (int r = 0; r < 4; r++) {
                    ulonglong2 vw = pwn[r][q], vq = pri[r][q], va = pa[r][q];
                    fma2(aH[r][0], ha.x, vw.x); fma2(aH[r][1], ha.y, vw.y);
                    fma2(aH[r][0], hb.x, vq.x); fma2(aH[r][1], hb.y, vq.y);
                    fma2(aH[r][0], hc.x, va.x); fma2(aH[r][1], hc.y, va.y);
                }
            }
#pragma unroll
            for (int r = 0; r < 4; r++) {
                float h = tanh_f(bh + red32(aH[r][0], aH[r][1]));
                float In = (1.f - zv[r]) * Iold[r] + zv[r] * h;
                if (kh == 0) S->sI[nb][R + r][js] = In;
            }
        }
        gbar(bid);

        // ---------- Phase 4: A gate + A_in -> A_new ----------
        {
            const ulonglong2* pin[4];
#pragma unroll
            for (int r = 0; r < 4; r++)
                pin[r] = (const ulonglong2*)(S->sI[nb][R + r] + khf);
            ull aA[4][2] = {}, aC[4][2] = {};
#pragma unroll
            for (int q = 0; q < 8; q++) {
                const int qw = khq + q;
                uint2 fa = S->Aff[0][qw][j]; ull fax = h2f2(fa.x), fay = h2f2(fa.y);
                uint2 fb = S->Aff[1][qw][j]; ull fbx = h2f2(fb.x), fby = h2f2(fb.y);
                uint2 fc = S->Aff[2][qw][j]; ull fcx = h2f2(fc.x), fcy = h2f2(fc.y);
                uint2 ga = S->Agt[0][qw][j]; ull gax = h2f2(ga.x), gay = h2f2(ga.y);
                uint2 gb = S->Agt[1][qw][j]; ull gbx = h2f2(gb.x), gby = h2f2(gb.y);
#pragma unroll
                for (int r = 0; r < 4; r++) {
                    ulonglong2 vw = pwn[r][q], vi = pin[r][q], va = pa[r][q];
                    fma2(aA[r][0], fax, vw.x); fma2(aA[r][1], fay, vw.y);
                    fma2(aC[r][0], gax, vw.x); fma2(aC[r][1], gay, vw.y);
                    fma2(aA[r][0], fbx, vi.x); fma2(aA[r][1], fby, vi.y);
                    fma2(aC[r][0], gbx, vi.x); fma2(aC[r][1], gby, vi.y);
                    fma2(aA[r][0], fcx, va.x); fma2(aA[r][1], fcy, va.y);
                }
            }
#pragma unroll
            for (int r = 0; r < 4; r++) {
                float ain = red32(aA[r][0], aA[r][1]);
                float gin = red32(aC[r][0], aC[r][1]);
                float An = tanh_f(ain) * sigm_f(ba + gin);
                if (kh == 0) S->sA[nb][R + r][js] = An;
            }
        }
        if (ltid < 32) S->xs[xrow][xc] = xv;   // stage x for t+1 (group rows)
        gbar(bid);

        // ---------- Phase 5: action = A_new @ phi + b (warp = row) ----------
        {
            const float* arow = S->sA[nb][wrow] + segoff;
            float4 v0 = *reinterpret_cast<const float4*>(arow);
            float4 v1 = *reinterpret_cast<const float4*>(arow + 4);
            float p = v0.x * ph[0];
            p = fmaf(v0.y, ph[1], p);
            p = fmaf(v0.z, ph[2], p);
            p = fmaf(v0.w, ph[3], p);
            p = fmaf(v1.x, ph[4], p);
            p = fmaf(v1.y, ph[5], p);
            p = fmaf(v1.z, ph[6], p);
            p = fmaf(v1.w, ph[7], p);
            p += __shfl_down_sync(0xffffffffu, p, 16);
            p += __shfl_down_sync(0xffffffffu, p, 8);
            p += __shfl_down_sync(0xffffffffu, p, 4);
            if (lane < 4)
                out[(base + wrow) * (TT * ODIM) + t * ODIM + o5] = p + bphi;
        }
    }
}

extern "C" void kernel_launch(void* const* d_in, const int* in_sizes, int n_in,
                              void* d_out, int out_size) {
    (void)in_sizes; (void)n_in; (void)out_size;
    const size_t shmem = sizeof(Smem);
    cudaFuncSetAttribute(anima_kernel,
                         cudaFuncAttributeMaxDynamicSharedMemorySize,
                         (int)shmem);
    anima_kernel<<<NCTA, NTHREADS, shmem>>>(
        (const float*)d_in[0],
        (const float*)d_in[1], (const float*)d_in[2],
        (const float*)d_in[3], (const float*)d_in[4], (const float*)d_in[5],
        (const float*)d_in[6], (const float*)d_in[7],
        (const float*)d_in[8], (const float*)d_in[9],
        (const float*)d_in[10], (const float*)d_in[11],
        (const float*)d_in[12], (const float*)d_in[13],
        (const float*)d_in[14], (const float*)d_in[15], (const float*)d_in[16],
        (const float*)d_in[17], (const float*)d_in[18],
        (const float*)d_in[19], (const float*)d_in[20],
        (float*)d_out);
}